// round 1
// baseline (speedup 1.0000x reference)
#include <cuda_runtime.h>
#include <math.h>

#define BB   2
#define SS   2048
#define HIDD 1024
#define NH   16
#define NKV  4
#define HD   64
#define SCALE 0.125f   // 1/sqrt(64)

// Scratch (static device globals — allocation-free)
__device__ float g_Q[BB*NH*SS*HD];      // 16 MB
__device__ float g_K[BB*NKV*SS*HD];     //  4 MB
__device__ float g_V[BB*NKV*SS*HD];     //  4 MB
__device__ float g_CTX[BB*SS*NH*HD];    // 16 MB

// ---------------------------------------------------------------------------
// Kernel 1: fused QKV projection GEMM + per-head RMSNorm + RoPE
// C[m, n] = X[m, :] . W[n, :],  n in [0,1536) = [Q 1024 | K 256 | V 256]
// Block: 64x64 output tile (one head per block-column), BK=16, 256 threads.
// ---------------------------------------------------------------------------
__global__ __launch_bounds__(256) void qkv_kernel(
    const float* __restrict__ X,  const float* __restrict__ Wq,
    const float* __restrict__ Wk, const float* __restrict__ Wv,
    const float* __restrict__ cosT, const float* __restrict__ sinT,
    const int*   __restrict__ pos,
    const float* __restrict__ qw, const float* __restrict__ kw)
{
    __shared__ float As[16][64];    // k-major
    __shared__ float Bs[16][64];    // k-major
    __shared__ float Cs[64][65];    // padded for row-scan epilogue

    const int tid = threadIdx.x;
    const int tx = tid & 15, ty = tid >> 4;
    const int m0 = blockIdx.y << 6;
    const int n0 = blockIdx.x << 6;

    const float* W; int mode, h;
    if (n0 < 1024)      { W = Wq + n0*HIDD;        mode = 0; h = n0 >> 6; }
    else if (n0 < 1280) { W = Wk + (n0-1024)*HIDD; mode = 1; h = (n0-1024) >> 6; }
    else                { W = Wv + (n0-1280)*HIDD; mode = 2; h = (n0-1280) >> 6; }

    const int lrow = tid >> 2;           // 0..63
    const int lcol = (tid & 3) << 2;     // 0,4,8,12
    const float* Ap = X + (m0 + lrow)*HIDD + lcol;
    const float* Bp = W + lrow*HIDD + lcol;

    float acc[4][4];
    #pragma unroll
    for (int i = 0; i < 4; i++)
        #pragma unroll
        for (int j = 0; j < 4; j++) acc[i][j] = 0.f;

    for (int k0 = 0; k0 < HIDD; k0 += 16) {
        float4 a = *(const float4*)(Ap + k0);
        float4 b = *(const float4*)(Bp + k0);
        __syncthreads();
        As[lcol+0][lrow] = a.x; As[lcol+1][lrow] = a.y;
        As[lcol+2][lrow] = a.z; As[lcol+3][lrow] = a.w;
        Bs[lcol+0][lrow] = b.x; Bs[lcol+1][lrow] = b.y;
        Bs[lcol+2][lrow] = b.z; Bs[lcol+3][lrow] = b.w;
        __syncthreads();
        #pragma unroll
        for (int kk = 0; kk < 16; kk++) {
            float4 av = *(const float4*)&As[kk][ty << 2];
            float4 bv = *(const float4*)&Bs[kk][tx << 2];
            float aa[4] = {av.x, av.y, av.z, av.w};
            float bb[4] = {bv.x, bv.y, bv.z, bv.w};
            #pragma unroll
            for (int i = 0; i < 4; i++)
                #pragma unroll
                for (int j = 0; j < 4; j++)
                    acc[i][j] = fmaf(aa[i], bb[j], acc[i][j]);
        }
    }

    __syncthreads();
    #pragma unroll
    for (int i = 0; i < 4; i++)
        #pragma unroll
        for (int j = 0; j < 4; j++)
            Cs[(ty<<2)+i][(tx<<2)+j] = acc[i][j];
    __syncthreads();

    // epilogue: one thread per row (64 rows); full head (64 cols) is in Cs
    if (tid < 64) {
        const int r    = tid;
        const int mrow = m0 + r;
        const int b    = mrow >> 11;       // / 2048
        const int srow = mrow & 2047;
        if (mode == 2) {
            float* dst = g_V + (((b*NKV + h)*SS + srow) << 6);
            #pragma unroll
            for (int d = 0; d < 64; d++) dst[d] = Cs[r][d];
        } else {
            float ss = 0.f;
            #pragma unroll
            for (int d = 0; d < 64; d++) { float v = Cs[r][d]; ss = fmaf(v, v, ss); }
            const float rstd = rsqrtf(ss * (1.f/64.f) + 1e-6f);
            const float* wn = (mode == 0) ? qw : kw;
            #pragma unroll
            for (int d = 0; d < 64; d++) Cs[r][d] = Cs[r][d] * rstd * wn[d];
            const int p = pos[b*SS + srow];
            const float* cr = cosT + (p << 6);
            const float* sr = sinT + (p << 6);
            float* dst = (mode == 0) ? (g_Q + (((b*NH  + h)*SS + srow) << 6))
                                     : (g_K + (((b*NKV + h)*SS + srow) << 6));
            #pragma unroll
            for (int d = 0; d < 32; d++) {
                float x1 = Cs[r][d], x2 = Cs[r][d+32];
                dst[d]    = x1*cr[d]    - x2*sr[d];
                dst[d+32] = x2*cr[d+32] + x1*sr[d+32];
            }
        }
    }
}

// ---------------------------------------------------------------------------
// Kernel 2: causal flash attention (fp32, online softmax).
// Block = one (b, h, 64-row q tile). 256 threads = 8 warps; warp w owns rows
// w*8..w*8+7; lane owns score/output cols {lane, lane+32}.
// K tile is XOR-swizzled (d ^ (c&31)) so stride-64 column reads are
// conflict-free; its buffer is reused for P after a barrier → 48 KB smem.
// ---------------------------------------------------------------------------
__global__ __launch_bounds__(256) void attn_kernel()
{
    __shared__ float Qs[64*64];
    __shared__ float KP[64*64];   // K (swizzled), then P (plain)
    __shared__ float Vs[64*64];

    const int tid  = threadIdx.x;
    const int lane = tid & 31;
    const int w    = tid >> 5;
    const int r0   = w << 3;
    const int qt = blockIdx.x, h = blockIdx.y, b = blockIdx.z;
    const int q0  = qt << 6;
    const int hkv = h >> 2;       // NH/NKV = 4

    const float* Qg = g_Q + (((b*NH  + h  )*SS + q0) << 6);
    const float* Kg = g_K + ( (b*NKV + hkv)*SS       << 6);
    const float* Vg = g_V + ( (b*NKV + hkv)*SS       << 6);

    #pragma unroll
    for (int i = 0; i < 4; i++) {
        int idx = tid + (i << 8);
        int r = idx >> 4, dc = (idx & 15) << 2;
        float4 q = *(const float4*)(Qg + (r << 6) + dc);
        float* d = &Qs[(r << 6) + dc];
        d[0] = q.x; d[1] = q.y; d[2] = q.z; d[3] = q.w;
    }

    float m[8], lsum[8], o0[8], o1[8];
    #pragma unroll
    for (int i = 0; i < 8; i++) { m[i] = -1e30f; lsum[i] = 0.f; o0[i] = 0.f; o1[i] = 0.f; }

    for (int kt = 0; kt <= qt; kt++) {
        __syncthreads();                       // prev-iter P/V reads done; Qs visible (1st iter)
        const float* Kt = Kg + (kt << 12);
        const float* Vt = Vg + (kt << 12);
        #pragma unroll
        for (int i = 0; i < 4; i++) {
            int idx = tid + (i << 8);
            int r = idx >> 4, dc = (idx & 15) << 2;
            float4 kv = *(const float4*)(Kt + (r << 6) + dc);
            int sw = r & 31;
            KP[(r << 6) + ((dc+0) ^ sw)] = kv.x;
            KP[(r << 6) + ((dc+1) ^ sw)] = kv.y;
            KP[(r << 6) + ((dc+2) ^ sw)] = kv.z;
            KP[(r << 6) + ((dc+3) ^ sw)] = kv.w;
            float4 vv = *(const float4*)(Vt + (r << 6) + dc);
            float* vd = &Vs[(r << 6) + dc];
            vd[0] = vv.x; vd[1] = vv.y; vd[2] = vv.z; vd[3] = vv.w;
        }
        __syncthreads();

        // S tile: rows r0..r0+7, cols {lane, lane+32}
        float s0[8], s1[8];
        #pragma unroll
        for (int i = 0; i < 8; i++) { s0[i] = 0.f; s1[i] = 0.f; }
        #pragma unroll 4
        for (int d = 0; d < 64; d++) {
            int dd = d ^ lane;                         // (lane+32)&31 == lane
            float k0 = KP[(lane << 6) + dd];
            float k1 = KP[((lane+32) << 6) + dd];
            #pragma unroll
            for (int i = 0; i < 8; i++) {
                float q = Qs[((r0+i) << 6) + d];
                s0[i] = fmaf(q, k0, s0[i]);
                s1[i] = fmaf(q, k1, s1[i]);
            }
        }
        __syncthreads();                       // all warps done reading K → KP becomes P

        const bool diag = (kt == qt);
        #pragma unroll
        for (int i = 0; i < 8; i++) {
            const int qrow = q0 + r0 + i;
            float a0 = s0[i]*SCALE, a1 = s1[i]*SCALE;
            if (diag) {
                int c = (kt << 6) + lane;
                if (c      > qrow) a0 = -1e30f;
                if (c + 32 > qrow) a1 = -1e30f;
            }
            float mx = fmaxf(a0, a1);
            #pragma unroll
            for (int off = 16; off > 0; off >>= 1)
                mx = fmaxf(mx, __shfl_xor_sync(0xffffffffu, mx, off));
            float nm    = fmaxf(m[i], mx);
            float alpha = __expf(m[i] - nm);
            float p0 = __expf(a0 - nm);
            float p1 = __expf(a1 - nm);
            float ps = p0 + p1;
            #pragma unroll
            for (int off = 16; off > 0; off >>= 1)
                ps += __shfl_xor_sync(0xffffffffu, ps, off);
            lsum[i] = lsum[i]*alpha + ps;
            m[i] = nm;
            o0[i] *= alpha; o1[i] *= alpha;
            KP[((r0+i) << 6) + lane     ] = p0;
            KP[((r0+i) << 6) + lane + 32] = p1;
        }
        __syncwarp();                          // P rows written/read by the same warp

        #pragma unroll 4
        for (int c = 0; c < 64; c++) {
            float v0 = Vs[(c << 6) + lane];
            float v1 = Vs[(c << 6) + lane + 32];
            #pragma unroll
            for (int i = 0; i < 8; i++) {
                float p = KP[((r0+i) << 6) + c];
                o0[i] = fmaf(p, v0, o0[i]);
                o1[i] = fmaf(p, v1, o1[i]);
            }
        }
    }

    float* Cg = g_CTX + ((b*SS + q0) << 10) + (h << 6);
    #pragma unroll
    for (int i = 0; i < 8; i++) {
        float inv = 1.f / lsum[i];
        float* dst = Cg + ((r0 + i) << 10);
        dst[lane]      = o0[i] * inv;
        dst[lane + 32] = o1[i] * inv;
    }
}

// ---------------------------------------------------------------------------
// Kernel 3: output projection  out[m,n] = CTX[m,:] . Wo[n,:]
// ---------------------------------------------------------------------------
__global__ __launch_bounds__(256) void out_kernel(
    const float* __restrict__ Wo, float* __restrict__ out)
{
    __shared__ float As[16][64];
    __shared__ float Bs[16][64];

    const int tid = threadIdx.x;
    const int tx = tid & 15, ty = tid >> 4;
    const int m0 = blockIdx.y << 6;
    const int n0 = blockIdx.x << 6;
    const int lrow = tid >> 2;
    const int lcol = (tid & 3) << 2;
    const float* Ap = g_CTX + (m0 + lrow)*1024 + lcol;
    const float* Bp = Wo    + (n0 + lrow)*1024 + lcol;

    float acc[4][4];
    #pragma unroll
    for (int i = 0; i < 4; i++)
        #pragma unroll
        for (int j = 0; j < 4; j++) acc[i][j] = 0.f;

    for (int k0 = 0; k0 < 1024; k0 += 16) {
        float4 a = *(const float4*)(Ap + k0);
        float4 b = *(const float4*)(Bp + k0);
        __syncthreads();
        As[lcol+0][lrow] = a.x; As[lcol+1][lrow] = a.y;
        As[lcol+2][lrow] = a.z; As[lcol+3][lrow] = a.w;
        Bs[lcol+0][lrow] = b.x; Bs[lcol+1][lrow] = b.y;
        Bs[lcol+2][lrow] = b.z; Bs[lcol+3][lrow] = b.w;
        __syncthreads();
        #pragma unroll
        for (int kk = 0; kk < 16; kk++) {
            float4 av = *(const float4*)&As[kk][ty << 2];
            float4 bv = *(const float4*)&Bs[kk][tx << 2];
            float aa[4] = {av.x, av.y, av.z, av.w};
            float bb[4] = {bv.x, bv.y, bv.z, bv.w};
            #pragma unroll
            for (int i = 0; i < 4; i++)
                #pragma unroll
                for (int j = 0; j < 4; j++)
                    acc[i][j] = fmaf(aa[i], bb[j], acc[i][j]);
        }
    }

    #pragma unroll
    for (int i = 0; i < 4; i++) {
        float4 st = {acc[i][0], acc[i][1], acc[i][2], acc[i][3]};
        *(float4*)&out[(m0 + (ty<<2) + i)*1024 + n0 + (tx<<2)] = st;
    }
}

// ---------------------------------------------------------------------------
extern "C" void kernel_launch(void* const* d_in, const int* in_sizes, int n_in,
                              void* d_out, int out_size)
{
    const float* X    = (const float*)d_in[0];
    const float* cosT = (const float*)d_in[1];
    const float* sinT = (const float*)d_in[2];
    const int*   pos  = (const int*)  d_in[3];
    // d_in[4] = attention_mask (causal; applied analytically)
    const float* Wq   = (const float*)d_in[5];
    const float* Wk   = (const float*)d_in[6];
    const float* Wv   = (const float*)d_in[7];
    const float* Wo   = (const float*)d_in[8];
    const float* qw   = (const float*)d_in[9];
    const float* kw   = (const float*)d_in[10];
    float* out = (float*)d_out;

    qkv_kernel<<<dim3(24, 64), 256>>>(X, Wq, Wk, Wv, cosT, sinT, pos, qw, kw);
    attn_kernel<<<dim3(SS/64, NH, BB), 256>>>();
    out_kernel<<<dim3(16, 64), 256>>>(Wo, out);
}

// round 2
// speedup vs baseline: 3.0285x; 3.0285x over previous
#include <cuda_runtime.h>
#include <math.h>

#define BB   2
#define SS   2048
#define HIDD 1024
#define NH   16
#define NKV  4
#define HD   64
#define SCALE 0.125f   // 1/sqrt(64)

// Scratch (static device globals — allocation-free)
__device__ float g_Q[BB*NH*SS*HD];      // 16 MB
__device__ float g_K[BB*NKV*SS*HD];     //  4 MB
__device__ float g_V[BB*NKV*SS*HD];     //  4 MB
__device__ float g_CTX[BB*SS*NH*HD];    // 16 MB

// ---------------------------------------------------------------------------
// tf32 helpers
// ---------------------------------------------------------------------------
__device__ __forceinline__ unsigned f2tf(float x) {
    unsigned r; asm("cvt.rna.tf32.f32 %0, %1;" : "=r"(r) : "f"(x)); return r;
}
__device__ __forceinline__ float f2tff(float x) { return __uint_as_float(f2tf(x)); }

// D += A*B, m16n8k8 tf32 (A row-major, B col-major)
__device__ __forceinline__ void mma8(float* c, const unsigned* a, const unsigned* b) {
    asm volatile(
        "mma.sync.aligned.m16n8k8.row.col.f32.tf32.tf32.f32 "
        "{%0,%1,%2,%3},{%4,%5,%6,%7},{%8,%9},{%0,%1,%2,%3};"
        : "+f"(c[0]), "+f"(c[1]), "+f"(c[2]), "+f"(c[3])
        : "r"(a[0]), "r"(a[1]), "r"(a[2]), "r"(a[3]), "r"(b[0]), "r"(b[1]));
}

// ---------------------------------------------------------------------------
// Kernel 1: QKV GEMM (tf32 MMA) + per-head RMSNorm + RoPE epilogue
// Block tile 128(M) x 64(N), BK=32, 256 threads = 8 warps (4m x 2n, 32x32 each)
// ---------------------------------------------------------------------------
__global__ __launch_bounds__(256) void qkv_kernel(
    const float* __restrict__ X,  const float* __restrict__ Wq,
    const float* __restrict__ Wk, const float* __restrict__ Wv,
    const float* __restrict__ cosT, const float* __restrict__ sinT,
    const int*   __restrict__ pos,
    const float* __restrict__ qw, const float* __restrict__ kw)
{
    __shared__ float sm[128*65];                 // union: {As,Bs} then Cs
    float* As = sm;                              // [128][36]
    float* Bs = sm + 128*36;                     // [64][36]

    const int tid  = threadIdx.x;
    const int lane = tid & 31;
    const int w    = tid >> 5;
    const int g = lane >> 2, t = lane & 3;
    const int wm = (w >> 1) << 5;                // 0,32,64,96
    const int wn = (w & 1) << 5;                 // 0,32
    const int m0 = blockIdx.y << 7;
    const int n0 = blockIdx.x << 6;

    const float* W; int mode, h;
    if (n0 < 1024)      { W = Wq + n0*HIDD;        mode = 0; h = n0 >> 6; }
    else if (n0 < 1280) { W = Wk + (n0-1024)*HIDD; mode = 1; h = (n0-1024) >> 6; }
    else                { W = Wv + (n0-1280)*HIDD; mode = 2; h = (n0-1280) >> 6; }

    float acc[2][4][4];
    #pragma unroll
    for (int i = 0; i < 2; i++)
        #pragma unroll
        for (int j = 0; j < 4; j++)
            #pragma unroll
            for (int e = 0; e < 4; e++) acc[i][j][e] = 0.f;

    // prefetch k0 = 0
    float4 ra[4], rb[2];
    #pragma unroll
    for (int i = 0; i < 4; i++) {
        int e = i*256 + tid;
        ra[i] = *(const float4*)(X + (m0 + (e >> 3))*HIDD + ((e & 7) << 2));
    }
    #pragma unroll
    for (int i = 0; i < 2; i++) {
        int e = i*256 + tid;
        rb[i] = *(const float4*)(W + (e >> 3)*HIDD + ((e & 7) << 2));
    }

    for (int k0 = 0; k0 < HIDD; k0 += 32) {
        __syncthreads();
        #pragma unroll
        for (int i = 0; i < 4; i++) {
            int e = i*256 + tid;
            float* d = &As[(e >> 3)*36 + ((e & 7) << 2)];
            d[0] = f2tff(ra[i].x); d[1] = f2tff(ra[i].y);
            d[2] = f2tff(ra[i].z); d[3] = f2tff(ra[i].w);
        }
        #pragma unroll
        for (int i = 0; i < 2; i++) {
            int e = i*256 + tid;
            float* d = &Bs[(e >> 3)*36 + ((e & 7) << 2)];
            d[0] = f2tff(rb[i].x); d[1] = f2tff(rb[i].y);
            d[2] = f2tff(rb[i].z); d[3] = f2tff(rb[i].w);
        }
        __syncthreads();
        if (k0 + 32 < HIDD) {
            #pragma unroll
            for (int i = 0; i < 4; i++) {
                int e = i*256 + tid;
                ra[i] = *(const float4*)(X + (m0 + (e >> 3))*HIDD + k0 + 32 + ((e & 7) << 2));
            }
            #pragma unroll
            for (int i = 0; i < 2; i++) {
                int e = i*256 + tid;
                rb[i] = *(const float4*)(W + (e >> 3)*HIDD + k0 + 32 + ((e & 7) << 2));
            }
        }
        #pragma unroll
        for (int ks = 0; ks < 4; ks++) {
            const int kb = ks << 3;
            unsigned a[2][4], b[4][2];
            #pragma unroll
            for (int i = 0; i < 2; i++) {
                const float* p = &As[(wm + i*16 + g)*36 + kb + t];
                a[i][0] = __float_as_uint(p[0]);
                a[i][1] = __float_as_uint(p[8*36]);
                a[i][2] = __float_as_uint(p[4]);
                a[i][3] = __float_as_uint(p[8*36 + 4]);
            }
            #pragma unroll
            for (int j = 0; j < 4; j++) {
                const float* p = &Bs[(wn + j*8 + g)*36 + kb + t];
                b[j][0] = __float_as_uint(p[0]);
                b[j][1] = __float_as_uint(p[4]);
            }
            #pragma unroll
            for (int i = 0; i < 2; i++)
                #pragma unroll
                for (int j = 0; j < 4; j++)
                    mma8(acc[i][j], a[i], b[j]);
        }
    }

    // stage C to smem (stride 65) for the row-wise epilogue
    __syncthreads();
    float* Cs = sm;
    #pragma unroll
    for (int i = 0; i < 2; i++)
        #pragma unroll
        for (int j = 0; j < 4; j++) {
            int r = wm + i*16 + g;
            int c = wn + j*8 + 2*t;
            Cs[r*65 + c]       = acc[i][j][0];
            Cs[r*65 + c + 1]   = acc[i][j][1];
            Cs[(r+8)*65 + c]   = acc[i][j][2];
            Cs[(r+8)*65 + c+1] = acc[i][j][3];
        }
    __syncthreads();

    if (tid < 128) {
        const int r    = tid;
        const int mrow = m0 + r;
        const int b    = mrow >> 11;
        const int srow = mrow & 2047;
        float* Crow = &Cs[r*65];
        if (mode == 2) {
            float* dst = g_V + (((b*NKV + h)*SS + srow) << 6);
            #pragma unroll
            for (int d = 0; d < 64; d++) dst[d] = Crow[d];
        } else {
            float ss = 0.f;
            #pragma unroll
            for (int d = 0; d < 64; d++) { float v = Crow[d]; ss = fmaf(v, v, ss); }
            const float rstd = rsqrtf(ss * (1.f/64.f) + 1e-6f);
            const float* wn2 = (mode == 0) ? qw : kw;
            #pragma unroll
            for (int d = 0; d < 64; d++) Crow[d] = Crow[d] * rstd * wn2[d];
            const int p = pos[b*SS + srow];
            const float* cr = cosT + (p << 6);
            const float* sr = sinT + (p << 6);
            float* dst = (mode == 0) ? (g_Q + (((b*NH  + h)*SS + srow) << 6))
                                     : (g_K + (((b*NKV + h)*SS + srow) << 6));
            #pragma unroll
            for (int d = 0; d < 32; d++) {
                float x1 = Crow[d], x2 = Crow[d+32];
                dst[d]    = x1*cr[d]    - x2*sr[d];
                dst[d+32] = x2*cr[d+32] + x1*sr[d+32];
            }
        }
    }
}

// ---------------------------------------------------------------------------
// Kernel 2: causal flash attention, tf32 MMA, online softmax on fragments.
// Block = (qt, h, b): 64 q-rows. 128 threads = 4 warps; warp w owns rows
// w*16..w*16+15.  KP buffer: K tile (stride 68), reused for P.  V stride 72.
// ---------------------------------------------------------------------------
__global__ __launch_bounds__(128) void attn_kernel()
{
    __shared__ float KP[64*68];
    __shared__ float Vs[64*72];

    const int tid  = threadIdx.x;
    const int lane = tid & 31;
    const int w    = tid >> 5;
    const int g = lane >> 2, t = lane & 3;
    const int qt = blockIdx.x, h = blockIdx.y, b = blockIdx.z;
    const int q0  = qt << 6;
    const int hkv = h >> 2;

    const float* Qg = g_Q + (((b*NH  + h  )*SS + q0 + w*16) << 6);
    const float* Kg = g_K + ( (b*NKV + hkv)*SS              << 6);
    const float* Vg = g_V + ( (b*NKV + hkv)*SS              << 6);

    // preload Q fragments (A operand) into registers, tf32-rounded
    unsigned aq[8][4];
    #pragma unroll
    for (int ks = 0; ks < 8; ks++) {
        aq[ks][0] = f2tf(Qg[ g      *64 + ks*8 + t]);
        aq[ks][1] = f2tf(Qg[(g + 8) *64 + ks*8 + t]);
        aq[ks][2] = f2tf(Qg[ g      *64 + ks*8 + t + 4]);
        aq[ks][3] = f2tf(Qg[(g + 8) *64 + ks*8 + t + 4]);
    }

    float oacc[8][4];
    #pragma unroll
    for (int j = 0; j < 8; j++)
        #pragma unroll
        for (int e = 0; e < 4; e++) oacc[j][e] = 0.f;
    float m_lo = -1e30f, m_hi = -1e30f, l_lo = 0.f, l_hi = 0.f;

    for (int kt = 0; kt <= qt; kt++) {
        __syncthreads();                         // prev PV / S reads done
        const float* Kt = Kg + (kt << 12);
        const float* Vt = Vg + (kt << 12);
        #pragma unroll
        for (int i = 0; i < 8; i++) {
            int e = i*128 + tid;
            int r = e >> 4, c = (e & 15) << 2;
            float4 kv = *(const float4*)(Kt + r*64 + c);
            float* d = &KP[r*68 + c];
            d[0] = f2tff(kv.x); d[1] = f2tff(kv.y);
            d[2] = f2tff(kv.z); d[3] = f2tff(kv.w);
            float4 vv = *(const float4*)(Vt + r*64 + c);
            float* d2 = &Vs[r*72 + c];
            d2[0] = f2tff(vv.x); d2[1] = f2tff(vv.y);
            d2[2] = f2tff(vv.z); d2[3] = f2tff(vv.w);
        }
        __syncthreads();

        // S = Q K^T : per warp 16x64
        float sacc[8][4];
        #pragma unroll
        for (int j = 0; j < 8; j++)
            #pragma unroll
            for (int e = 0; e < 4; e++) sacc[j][e] = 0.f;
        #pragma unroll
        for (int ks = 0; ks < 8; ks++) {
            #pragma unroll
            for (int j = 0; j < 8; j++) {
                unsigned bk[2];
                const float* p = &KP[(j*8 + g)*68 + ks*8 + t];
                bk[0] = __float_as_uint(p[0]);
                bk[1] = __float_as_uint(p[4]);
                mma8(sacc[j], aq[ks], bk);
            }
        }

        // online softmax on fragments (rows g / g+8 of this warp's band)
        const bool diag = (kt == qt);
        float mx_lo = -1e30f, mx_hi = -1e30f;
        #pragma unroll
        for (int j = 0; j < 8; j++) {
            #pragma unroll
            for (int e = 0; e < 4; e++) {
                float s = sacc[j][e] * SCALE;
                if (diag) {
                    int c = j*8 + 2*t + (e & 1);
                    int r = w*16 + g + ((e >> 1) << 3);
                    if (c > r) s = -1e30f;
                }
                sacc[j][e] = s;
            }
            mx_lo = fmaxf(mx_lo, fmaxf(sacc[j][0], sacc[j][1]));
            mx_hi = fmaxf(mx_hi, fmaxf(sacc[j][2], sacc[j][3]));
        }
        mx_lo = fmaxf(mx_lo, __shfl_xor_sync(0xffffffffu, mx_lo, 1));
        mx_lo = fmaxf(mx_lo, __shfl_xor_sync(0xffffffffu, mx_lo, 2));
        mx_hi = fmaxf(mx_hi, __shfl_xor_sync(0xffffffffu, mx_hi, 1));
        mx_hi = fmaxf(mx_hi, __shfl_xor_sync(0xffffffffu, mx_hi, 2));

        float nm_lo = fmaxf(m_lo, mx_lo), nm_hi = fmaxf(m_hi, mx_hi);
        float al_lo = __expf(m_lo - nm_lo), al_hi = __expf(m_hi - nm_hi);
        m_lo = nm_lo; m_hi = nm_hi;

        float sum_lo = 0.f, sum_hi = 0.f;
        #pragma unroll
        for (int j = 0; j < 8; j++) {
            sacc[j][0] = __expf(sacc[j][0] - nm_lo);
            sacc[j][1] = __expf(sacc[j][1] - nm_lo);
            sacc[j][2] = __expf(sacc[j][2] - nm_hi);
            sacc[j][3] = __expf(sacc[j][3] - nm_hi);
            sum_lo += sacc[j][0] + sacc[j][1];
            sum_hi += sacc[j][2] + sacc[j][3];
        }
        sum_lo += __shfl_xor_sync(0xffffffffu, sum_lo, 1);
        sum_lo += __shfl_xor_sync(0xffffffffu, sum_lo, 2);
        sum_hi += __shfl_xor_sync(0xffffffffu, sum_hi, 1);
        sum_hi += __shfl_xor_sync(0xffffffffu, sum_hi, 2);
        l_lo = l_lo*al_lo + sum_lo;
        l_hi = l_hi*al_hi + sum_hi;
        #pragma unroll
        for (int j = 0; j < 8; j++) {
            oacc[j][0] *= al_lo; oacc[j][1] *= al_lo;
            oacc[j][2] *= al_hi; oacc[j][3] *= al_hi;
        }

        __syncthreads();                         // all warps done reading K
        // store P (tf32) into freed K buffer, own rows only
        #pragma unroll
        for (int j = 0; j < 8; j++) {
            int c = j*8 + 2*t;
            int r = w*16 + g;
            KP[r*68 + c]         = f2tff(sacc[j][0]);
            KP[r*68 + c + 1]     = f2tff(sacc[j][1]);
            KP[(r+8)*68 + c]     = f2tff(sacc[j][2]);
            KP[(r+8)*68 + c + 1] = f2tff(sacc[j][3]);
        }
        __syncwarp();

        // O += P V : per warp 16x64
        #pragma unroll
        for (int ks = 0; ks < 8; ks++) {
            unsigned ap[4];
            const float* p = &KP[(w*16 + g)*68 + ks*8 + t];
            ap[0] = __float_as_uint(p[0]);
            ap[1] = __float_as_uint(p[8*68]);
            ap[2] = __float_as_uint(p[4]);
            ap[3] = __float_as_uint(p[8*68 + 4]);
            #pragma unroll
            for (int j = 0; j < 8; j++) {
                unsigned bv[2];
                const float* q = &Vs[(ks*8 + t)*72 + j*8 + g];
                bv[0] = __float_as_uint(q[0]);
                bv[1] = __float_as_uint(q[4*72]);
                mma8(oacc[j], ap, bv);
            }
        }
    }

    const float inv_lo = 1.f / l_lo, inv_hi = 1.f / l_hi;
    float* Cg = g_CTX + ((b*SS + q0 + w*16) << 10) + (h << 6);
    #pragma unroll
    for (int j = 0; j < 8; j++) {
        int c = j*8 + 2*t;
        float2 v0 = { oacc[j][0]*inv_lo, oacc[j][1]*inv_lo };
        *(float2*)&Cg[g*1024 + c] = v0;
        float2 v1 = { oacc[j][2]*inv_hi, oacc[j][3]*inv_hi };
        *(float2*)&Cg[(g+8)*1024 + c] = v1;
    }
}

// ---------------------------------------------------------------------------
// Kernel 3: output projection (tf32 MMA), direct fragment stores
// ---------------------------------------------------------------------------
__global__ __launch_bounds__(256) void out_kernel(
    const float* __restrict__ Wo, float* __restrict__ out)
{
    __shared__ float sm[128*36 + 64*36];
    float* As = sm;
    float* Bs = sm + 128*36;

    const int tid  = threadIdx.x;
    const int lane = tid & 31;
    const int w    = tid >> 5;
    const int g = lane >> 2, t = lane & 3;
    const int wm = (w >> 1) << 5;
    const int wn = (w & 1) << 5;
    const int m0 = blockIdx.y << 7;
    const int n0 = blockIdx.x << 6;

    float acc[2][4][4];
    #pragma unroll
    for (int i = 0; i < 2; i++)
        #pragma unroll
        for (int j = 0; j < 4; j++)
            #pragma unroll
            for (int e = 0; e < 4; e++) acc[i][j][e] = 0.f;

    float4 ra[4], rb[2];
    #pragma unroll
    for (int i = 0; i < 4; i++) {
        int e = i*256 + tid;
        ra[i] = *(const float4*)(g_CTX + (m0 + (e >> 3))*1024 + ((e & 7) << 2));
    }
    #pragma unroll
    for (int i = 0; i < 2; i++) {
        int e = i*256 + tid;
        rb[i] = *(const float4*)(Wo + (n0 + (e >> 3))*1024 + ((e & 7) << 2));
    }

    for (int k0 = 0; k0 < 1024; k0 += 32) {
        __syncthreads();
        #pragma unroll
        for (int i = 0; i < 4; i++) {
            int e = i*256 + tid;
            float* d = &As[(e >> 3)*36 + ((e & 7) << 2)];
            d[0] = f2tff(ra[i].x); d[1] = f2tff(ra[i].y);
            d[2] = f2tff(ra[i].z); d[3] = f2tff(ra[i].w);
        }
        #pragma unroll
        for (int i = 0; i < 2; i++) {
            int e = i*256 + tid;
            float* d = &Bs[(e >> 3)*36 + ((e & 7) << 2)];
            d[0] = f2tff(rb[i].x); d[1] = f2tff(rb[i].y);
            d[2] = f2tff(rb[i].z); d[3] = f2tff(rb[i].w);
        }
        __syncthreads();
        if (k0 + 32 < 1024) {
            #pragma unroll
            for (int i = 0; i < 4; i++) {
                int e = i*256 + tid;
                ra[i] = *(const float4*)(g_CTX + (m0 + (e >> 3))*1024 + k0 + 32 + ((e & 7) << 2));
            }
            #pragma unroll
            for (int i = 0; i < 2; i++) {
                int e = i*256 + tid;
                rb[i] = *(const float4*)(Wo + (n0 + (e >> 3))*1024 + k0 + 32 + ((e & 7) << 2));
            }
        }
        #pragma unroll
        for (int ks = 0; ks < 4; ks++) {
            const int kb = ks << 3;
            unsigned a[2][4], b[4][2];
            #pragma unroll
            for (int i = 0; i < 2; i++) {
                const float* p = &As[(wm + i*16 + g)*36 + kb + t];
                a[i][0] = __float_as_uint(p[0]);
                a[i][1] = __float_as_uint(p[8*36]);
                a[i][2] = __float_as_uint(p[4]);
                a[i][3] = __float_as_uint(p[8*36 + 4]);
            }
            #pragma unroll
            for (int j = 0; j < 4; j++) {
                const float* p = &Bs[(wn + j*8 + g)*36 + kb + t];
                b[j][0] = __float_as_uint(p[0]);
                b[j][1] = __float_as_uint(p[4]);
            }
            #pragma unroll
            for (int i = 0; i < 2; i++)
                #pragma unroll
                for (int j = 0; j < 4; j++)
                    mma8(acc[i][j], a[i], b[j]);
        }
    }

    #pragma unroll
    for (int i = 0; i < 2; i++)
        #pragma unroll
        for (int j = 0; j < 4; j++) {
            int r = m0 + wm + i*16 + g;
            int c = n0 + wn + j*8 + 2*t;
            float2 v0 = { acc[i][j][0], acc[i][j][1] };
            *(float2*)&out[r*1024 + c] = v0;
            float2 v1 = { acc[i][j][2], acc[i][j][3] };
            *(float2*)&out[(r+8)*1024 + c] = v1;
        }
}

// ---------------------------------------------------------------------------
extern "C" void kernel_launch(void* const* d_in, const int* in_sizes, int n_in,
                              void* d_out, int out_size)
{
    const float* X    = (const float*)d_in[0];
    const float* cosT = (const float*)d_in[1];
    const float* sinT = (const float*)d_in[2];
    const int*   pos  = (const int*)  d_in[3];
    // d_in[4] = attention_mask (causal; applied analytically)
    const float* Wq   = (const float*)d_in[5];
    const float* Wk   = (const float*)d_in[6];
    const float* Wv   = (const float*)d_in[7];
    const float* Wo   = (const float*)d_in[8];
    const float* qw   = (const float*)d_in[9];
    const float* kw   = (const float*)d_in[10];
    float* out = (float*)d_out;

    qkv_kernel<<<dim3(24, 32), 256>>>(X, Wq, Wk, Wv, cosT, sinT, pos, qw, kw);
    attn_kernel<<<dim3(SS/64, NH, BB), 128>>>();
    out_kernel<<<dim3(16, 32), 256>>>(Wo, out);
}

// round 3
// speedup vs baseline: 3.1530x; 1.0411x over previous
#include <cuda_runtime.h>

#define BB   2
#define SS   2048
#define HIDD 1024
#define NH   16
#define NKV  4
#define HD   64
#define SCALE 0.125f   // 1/sqrt(64)

// Scratch (static device globals — allocation-free)
__device__ float g_Q[BB*NH*SS*HD];        // 16 MB (tf32-rounded)
__device__ float g_K[BB*NKV*SS*HD];       //  4 MB (tf32-rounded)
__device__ float g_V[BB*NKV*SS*HD];       //  4 MB (tf32-rounded)
__device__ float g_CTX[BB*SS*NH*HD];      // 16 MB (tf32-rounded)
__device__ float g_Xt[BB*SS*HIDD];        // 16 MB tf32 copy of X
__device__ float g_Wt[1536*HIDD];         //  6 MB tf32 [Wq;Wk;Wv]
__device__ float g_Wot[HIDD*HIDD];        //  4 MB tf32 Wo

// ---------------------------------------------------------------------------
// helpers
// ---------------------------------------------------------------------------
__device__ __forceinline__ unsigned f2tf(float x) {
    unsigned r; asm("cvt.rna.tf32.f32 %0, %1;" : "=r"(r) : "f"(x)); return r;
}
__device__ __forceinline__ float f2tff(float x) { return __uint_as_float(f2tf(x)); }

__device__ __forceinline__ void mma8(float* c, const unsigned* a, const unsigned* b) {
    asm volatile(
        "mma.sync.aligned.m16n8k8.row.col.f32.tf32.tf32.f32 "
        "{%0,%1,%2,%3},{%4,%5,%6,%7},{%8,%9},{%0,%1,%2,%3};"
        : "+f"(c[0]), "+f"(c[1]), "+f"(c[2]), "+f"(c[3])
        : "r"(a[0]), "r"(a[1]), "r"(a[2]), "r"(a[3]), "r"(b[0]), "r"(b[1]));
}

__device__ __forceinline__ void cp16(float* dst, const float* src) {
    unsigned d = (unsigned)__cvta_generic_to_shared(dst);
    asm volatile("cp.async.cg.shared.global [%0], [%1], 16;\n" :: "r"(d), "l"(src));
}
__device__ __forceinline__ void cpcommit() { asm volatile("cp.async.commit_group;\n"); }
__device__ __forceinline__ void cpwait0()  { asm volatile("cp.async.wait_group 0;\n" ::: "memory"); }
__device__ __forceinline__ void cpwait1()  { asm volatile("cp.async.wait_group 1;\n" ::: "memory"); }

// ---------------------------------------------------------------------------
// Kernel 0: one-time tf32 rounding of X / Wq / Wk / Wv / Wo
// ---------------------------------------------------------------------------
__global__ __launch_bounds__(256) void cvt_kernel(
    const float* __restrict__ X,  const float* __restrict__ Wq,
    const float* __restrict__ Wk, const float* __restrict__ Wv,
    const float* __restrict__ Wo)
{
    long i = (long)blockIdx.x * 256 + threadIdx.x;   // float4 index
    const float4* src; float4* dst;
    if (i < 1048576L)       { src = (const float4*)X  + i;             dst = (float4*)g_Xt  + i; }
    else if (i < 1310720L)  { long j = i - 1048576L; src = (const float4*)Wq + j; dst = (float4*)g_Wt + j; }
    else if (i < 1376256L)  { long j = i - 1310720L; src = (const float4*)Wk + j; dst = (float4*)g_Wt + 262144L + j; }
    else if (i < 1441792L)  { long j = i - 1376256L; src = (const float4*)Wv + j; dst = (float4*)g_Wt + 327680L + j; }
    else                    { long j = i - 1441792L; src = (const float4*)Wo + j; dst = (float4*)g_Wot + j; }
    float4 v = *src;
    *dst = make_float4(f2tff(v.x), f2tff(v.y), f2tff(v.z), f2tff(v.w));
}

// ---------------------------------------------------------------------------
// GEMM core config: block 128(M) x 64(N), BK=32, 128 threads = 4 warps
// (2m x 2n), warp tile 64x32.  2-stage cp.async pipeline, smem stride 36.
// stage s: As = sm + s*6912 (128x36), Bs = As + 4608 (64x36)
// ---------------------------------------------------------------------------
#define GEMM_STAGE_F 6912

__device__ __forceinline__ void gemm_stage(float* sm, int s, int k0,
                                           const float* A, const float* B, int tid)
{
    float* As = sm + s*GEMM_STAGE_F;
    float* Bs = As + 4608;
    #pragma unroll
    for (int q = 0; q < 8; q++) {
        int e = q*128 + tid; int r = e >> 3, c = (e & 7) << 2;
        cp16(As + r*36 + c, A + (long)r*HIDD + k0 + c);
    }
    #pragma unroll
    for (int q = 0; q < 4; q++) {
        int e = q*128 + tid; int r = e >> 3, c = (e & 7) << 2;
        cp16(Bs + r*36 + c, B + (long)r*HIDD + k0 + c);
    }
    cpcommit();
}

__device__ __forceinline__ void gemm_body(float* sm, const float* A, const float* B,
                                          float acc[4][4][4], int tid)
{
    const int lane = tid & 31, w = tid >> 5;
    const int g = lane >> 2, t = lane & 3;
    const int wm = (w >> 1) << 6;     // 0 or 64
    const int wn = (w & 1) << 5;      // 0 or 32

    gemm_stage(sm, 0, 0,  A, B, tid);
    gemm_stage(sm, 1, 32, A, B, tid);

    for (int kt = 0; kt < 32; kt++) {
        const int s = kt & 1;
        if (kt == 31) cpwait0(); else cpwait1();
        __syncthreads();
        const float* As = sm + s*GEMM_STAGE_F;
        const float* Bs = As + 4608;
        #pragma unroll
        for (int ks = 0; ks < 4; ks++) {
            const int kb = ks << 3;
            unsigned a[4][4], b[4][2];
            #pragma unroll
            for (int i = 0; i < 4; i++) {
                const float* p = &As[(wm + i*16 + g)*36 + kb + t];
                a[i][0] = __float_as_uint(p[0]);
                a[i][1] = __float_as_uint(p[8*36]);
                a[i][2] = __float_as_uint(p[4]);
                a[i][3] = __float_as_uint(p[8*36 + 4]);
            }
            #pragma unroll
            for (int j = 0; j < 4; j++) {
                const float* p = &Bs[(wn + j*8 + g)*36 + kb + t];
                b[j][0] = __float_as_uint(p[0]);
                b[j][1] = __float_as_uint(p[4]);
            }
            #pragma unroll
            for (int i = 0; i < 4; i++)
                #pragma unroll
                for (int j = 0; j < 4; j++)
                    mma8(acc[i][j], a[i], b[j]);
        }
        __syncthreads();
        if (kt + 2 < 32) gemm_stage(sm, s, (kt + 2) << 5, A, B, tid);
    }
}

// ---------------------------------------------------------------------------
// Kernel 1: QKV GEMM + per-head RMSNorm + RoPE epilogue
// ---------------------------------------------------------------------------
__global__ __launch_bounds__(128) void qkv_kernel(
    const float* __restrict__ cosT, const float* __restrict__ sinT,
    const int*   __restrict__ pos,
    const float* __restrict__ qw, const float* __restrict__ kw)
{
    extern __shared__ float sm[];
    const int tid  = threadIdx.x;
    const int lane = tid & 31, w = tid >> 5;
    const int g = lane >> 2, t = lane & 3;
    const int wm = (w >> 1) << 6;
    const int wn = (w & 1) << 5;
    const int m0 = blockIdx.y << 7;
    const int n0 = blockIdx.x << 6;

    int mode, h;
    if (n0 < 1024)      { mode = 0; h = n0 >> 6; }
    else if (n0 < 1280) { mode = 1; h = (n0-1024) >> 6; }
    else                { mode = 2; h = (n0-1280) >> 6; }

    const float* A = g_Xt + (long)m0*HIDD;
    const float* B = g_Wt + (long)n0*HIDD;

    float acc[4][4][4];
    #pragma unroll
    for (int i = 0; i < 4; i++)
        #pragma unroll
        for (int j = 0; j < 4; j++)
            #pragma unroll
            for (int e = 0; e < 4; e++) acc[i][j][e] = 0.f;

    gemm_body(sm, A, B, acc, tid);

    // stage C to smem (stride 65) for row-wise epilogue
    __syncthreads();
    float* Cs = sm;
    #pragma unroll
    for (int i = 0; i < 4; i++)
        #pragma unroll
        for (int j = 0; j < 4; j++) {
            int r = wm + i*16 + g;
            int c = wn + j*8 + 2*t;
            Cs[r*65 + c]         = acc[i][j][0];
            Cs[r*65 + c + 1]     = acc[i][j][1];
            Cs[(r+8)*65 + c]     = acc[i][j][2];
            Cs[(r+8)*65 + c + 1] = acc[i][j][3];
        }
    __syncthreads();

    {
        const int r    = tid;              // 128 threads, 128 rows
        const int mrow = m0 + r;
        const int b    = mrow >> 11;
        const int srow = mrow & 2047;
        float* Crow = &Cs[r*65];
        if (mode == 2) {
            float* dst = g_V + (((b*NKV + h)*SS + srow) << 6);
            #pragma unroll
            for (int d = 0; d < 64; d++) dst[d] = f2tff(Crow[d]);
        } else {
            float ssum = 0.f;
            #pragma unroll
            for (int d = 0; d < 64; d++) { float v = Crow[d]; ssum = fmaf(v, v, ssum); }
            const float rstd = rsqrtf(ssum * (1.f/64.f) + 1e-6f);
            const float* wn2 = (mode == 0) ? qw : kw;
            #pragma unroll
            for (int d = 0; d < 64; d++) Crow[d] = Crow[d] * rstd * wn2[d];
            const int p = pos[b*SS + srow];
            const float* cr = cosT + (p << 6);
            const float* sr = sinT + (p << 6);
            float* dst = (mode == 0) ? (g_Q + (((b*NH  + h)*SS + srow) << 6))
                                     : (g_K + (((b*NKV + h)*SS + srow) << 6));
            #pragma unroll
            for (int d = 0; d < 32; d++) {
                float x1 = Crow[d], x2 = Crow[d+32];
                dst[d]    = f2tff(x1*cr[d]    - x2*sr[d]);
                dst[d+32] = f2tff(x2*cr[d+32] + x1*sr[d+32]);
            }
        }
    }
}

// ---------------------------------------------------------------------------
// Kernel 2: causal flash attention, tf32 MMA, q-tile 128, 8 warps.
// smem: K[2][64*68] | V[2][64*72] | P[128*68]; cp.async double-buffered K/V.
// warp w owns q rows w*16..w*16+15.
// ---------------------------------------------------------------------------
__global__ __launch_bounds__(256, 2) void attn_kernel()
{
    extern __shared__ float sm[];
    float* Kb = sm;                    // [2][64*68]
    float* Vb = sm + 2*4352;           // [2][64*72]
    float* Ps = sm + 2*4352 + 2*4608;  // [128*68]

    const int tid  = threadIdx.x;
    const int lane = tid & 31;
    const int w    = tid >> 5;
    const int g = lane >> 2, t = lane & 3;
    const int qt = gridDim.x - 1 - blockIdx.x;   // heavy tiles first
    const int h = blockIdx.y, b = blockIdx.z;
    const int q0  = qt << 7;
    const int hkv = h >> 2;

    const float* Qg = g_Q + (((b*NH  + h  )*SS + q0 + w*16) << 6);
    const float* Kg = g_K + ( (b*NKV + hkv)*SS              << 6);
    const float* Vg = g_V + ( (b*NKV + hkv)*SS              << 6);

    // preload Q fragments (pre-rounded tf32)
    unsigned aq[8][4];
    #pragma unroll
    for (int ks = 0; ks < 8; ks++) {
        aq[ks][0] = __float_as_uint(Qg[ g      *64 + ks*8 + t]);
        aq[ks][1] = __float_as_uint(Qg[(g + 8) *64 + ks*8 + t]);
        aq[ks][2] = __float_as_uint(Qg[ g      *64 + ks*8 + t + 4]);
        aq[ks][3] = __float_as_uint(Qg[(g + 8) *64 + ks*8 + t + 4]);
    }

    float oacc[8][4];
    #pragma unroll
    for (int j = 0; j < 8; j++)
        #pragma unroll
        for (int e = 0; e < 4; e++) oacc[j][e] = 0.f;
    float m_lo = -1e30f, m_hi = -1e30f, l_lo = 0.f, l_hi = 0.f;

    const int nkt = 2*qt + 2;

    // prologue: stage tile 0 into buf 0
    {
        #pragma unroll
        for (int q = 0; q < 4; q++) {
            int e = q*256 + tid; int r = e >> 4, c = (e & 15) << 2;
            cp16(Kb + r*68 + c, Kg + r*64 + c);
            cp16(Vb + r*72 + c, Vg + r*64 + c);
        }
        cpcommit();
    }

    for (int kt = 0; kt < nkt; kt++) {
        const int s = kt & 1;
        const bool hasNext = (kt + 1 < nkt);
        __syncthreads();                 // all warps done reading buf s^1 (tile kt-1)
        if (hasNext) {
            const float* Kt = Kg + ((kt+1) << 12);
            const float* Vt = Vg + ((kt+1) << 12);
            float* Kd = Kb + (s^1)*4352;
            float* Vd = Vb + (s^1)*4608;
            #pragma unroll
            for (int q = 0; q < 4; q++) {
                int e = q*256 + tid; int r = e >> 4, c = (e & 15) << 2;
                cp16(Kd + r*68 + c, Kt + r*64 + c);
                cp16(Vd + r*72 + c, Vt + r*64 + c);
            }
            cpcommit();
            cpwait1();
        } else {
            cpwait0();
        }
        __syncthreads();                 // tile kt visible to all

        // skip warps whose entire row band is masked for this kv tile
        if ((kt << 6) > q0 + w*16 + 15) continue;

        const float* Kc = Kb + s*4352;
        const float* Vc = Vb + s*4608;

        // S = Q K^T : 16x64 per warp
        float sacc[8][4];
        #pragma unroll
        for (int j = 0; j < 8; j++)
            #pragma unroll
            for (int e = 0; e < 4; e++) sacc[j][e] = 0.f;
        #pragma unroll
        for (int ks = 0; ks < 8; ks++) {
            #pragma unroll
            for (int j = 0; j < 8; j++) {
                unsigned bk[2];
                const float* p = &Kc[(j*8 + g)*68 + ks*8 + t];
                bk[0] = __float_as_uint(p[0]);
                bk[1] = __float_as_uint(p[4]);
                mma8(sacc[j], aq[ks], bk);
            }
        }

        const bool diag = ((kt << 6) + 63 > q0 + w*16);
        float mx_lo = -1e30f, mx_hi = -1e30f;
        #pragma unroll
        for (int j = 0; j < 8; j++) {
            #pragma unroll
            for (int e = 0; e < 4; e++) {
                float s2 = sacc[j][e] * SCALE;
                if (diag) {
                    int c = (kt << 6) + j*8 + 2*t + (e & 1);
                    int r = q0 + w*16 + g + ((e >> 1) << 3);
                    if (c > r) s2 = -1e30f;
                }
                sacc[j][e] = s2;
            }
            mx_lo = fmaxf(mx_lo, fmaxf(sacc[j][0], sacc[j][1]));
            mx_hi = fmaxf(mx_hi, fmaxf(sacc[j][2], sacc[j][3]));
        }
        mx_lo = fmaxf(mx_lo, __shfl_xor_sync(0xffffffffu, mx_lo, 1));
        mx_lo = fmaxf(mx_lo, __shfl_xor_sync(0xffffffffu, mx_lo, 2));
        mx_hi = fmaxf(mx_hi, __shfl_xor_sync(0xffffffffu, mx_hi, 1));
        mx_hi = fmaxf(mx_hi, __shfl_xor_sync(0xffffffffu, mx_hi, 2));

        float nm_lo = fmaxf(m_lo, mx_lo), nm_hi = fmaxf(m_hi, mx_hi);
        float al_lo = __expf(m_lo - nm_lo), al_hi = __expf(m_hi - nm_hi);
        m_lo = nm_lo; m_hi = nm_hi;

        float sum_lo = 0.f, sum_hi = 0.f;
        #pragma unroll
        for (int j = 0; j < 8; j++) {
            sacc[j][0] = __expf(sacc[j][0] - nm_lo);
            sacc[j][1] = __expf(sacc[j][1] - nm_lo);
            sacc[j][2] = __expf(sacc[j][2] - nm_hi);
            sacc[j][3] = __expf(sacc[j][3] - nm_hi);
            sum_lo += sacc[j][0] + sacc[j][1];
            sum_hi += sacc[j][2] + sacc[j][3];
        }
        sum_lo += __shfl_xor_sync(0xffffffffu, sum_lo, 1);
        sum_lo += __shfl_xor_sync(0xffffffffu, sum_lo, 2);
        sum_hi += __shfl_xor_sync(0xffffffffu, sum_hi, 1);
        sum_hi += __shfl_xor_sync(0xffffffffu, sum_hi, 2);
        l_lo = l_lo*al_lo + sum_lo;
        l_hi = l_hi*al_hi + sum_hi;
        #pragma unroll
        for (int j = 0; j < 8; j++) {
            oacc[j][0] *= al_lo; oacc[j][1] *= al_lo;
            oacc[j][2] *= al_hi; oacc[j][3] *= al_hi;
        }

        // store P (tf32) into per-warp rows of the dedicated P buffer
        #pragma unroll
        for (int j = 0; j < 8; j++) {
            int c = j*8 + 2*t;
            int r = w*16 + g;
            Ps[r*68 + c]         = f2tff(sacc[j][0]);
            Ps[r*68 + c + 1]     = f2tff(sacc[j][1]);
            Ps[(r+8)*68 + c]     = f2tff(sacc[j][2]);
            Ps[(r+8)*68 + c + 1] = f2tff(sacc[j][3]);
        }
        __syncwarp();

        // O += P V : 16x64 per warp
        #pragma unroll
        for (int ks = 0; ks < 8; ks++) {
            unsigned ap[4];
            const float* p = &Ps[(w*16 + g)*68 + ks*8 + t];
            ap[0] = __float_as_uint(p[0]);
            ap[1] = __float_as_uint(p[8*68]);
            ap[2] = __float_as_uint(p[4]);
            ap[3] = __float_as_uint(p[8*68 + 4]);
            #pragma unroll
            for (int j = 0; j < 8; j++) {
                unsigned bv[2];
                const float* q = &Vc[(ks*8 + t)*72 + j*8 + g];
                bv[0] = __float_as_uint(q[0]);
                bv[1] = __float_as_uint(q[4*72]);
                mma8(oacc[j], ap, bv);
            }
        }
    }

    const float inv_lo = 1.f / l_lo, inv_hi = 1.f / l_hi;
    float* Cg = g_CTX + ((b*SS + q0 + w*16) << 10) + (h << 6);
    #pragma unroll
    for (int j = 0; j < 8; j++) {
        int c = j*8 + 2*t;
        float2 v0 = { f2tff(oacc[j][0]*inv_lo), f2tff(oacc[j][1]*inv_lo) };
        *(float2*)&Cg[g*1024 + c] = v0;
        float2 v1 = { f2tff(oacc[j][2]*inv_hi), f2tff(oacc[j][3]*inv_hi) };
        *(float2*)&Cg[(g+8)*1024 + c] = v1;
    }
}

// ---------------------------------------------------------------------------
// Kernel 3: output projection, direct fragment stores
// ---------------------------------------------------------------------------
__global__ __launch_bounds__(128) void out_kernel(float* __restrict__ out)
{
    extern __shared__ float sm[];
    const int tid  = threadIdx.x;
    const int lane = tid & 31, w = tid >> 5;
    const int g = lane >> 2, t = lane & 3;
    const int wm = (w >> 1) << 6;
    const int wn = (w & 1) << 5;
    const int m0 = blockIdx.y << 7;
    const int n0 = blockIdx.x << 6;

    const float* A = g_CTX + (long)m0*HIDD;
    const float* B = g_Wot + (long)n0*HIDD;

    float acc[4][4][4];
    #pragma unroll
    for (int i = 0; i < 4; i++)
        #pragma unroll
        for (int j = 0; j < 4; j++)
            #pragma unroll
            for (int e = 0; e < 4; e++) acc[i][j][e] = 0.f;

    gemm_body(sm, A, B, acc, tid);

    #pragma unroll
    for (int i = 0; i < 4; i++)
        #pragma unroll
        for (int j = 0; j < 4; j++) {
            int r = m0 + wm + i*16 + g;
            int c = n0 + wn + j*8 + 2*t;
            float2 v0 = { acc[i][j][0], acc[i][j][1] };
            *(float2*)&out[(long)r*1024 + c] = v0;
            float2 v1 = { acc[i][j][2], acc[i][j][3] };
            *(float2*)&out[(long)(r+8)*1024 + c] = v1;
        }
}

// ---------------------------------------------------------------------------
extern "C" void kernel_launch(void* const* d_in, const int* in_sizes, int n_in,
                              void* d_out, int out_size)
{
    const float* X    = (const float*)d_in[0];
    const float* cosT = (const float*)d_in[1];
    const float* sinT = (const float*)d_in[2];
    const int*   pos  = (const int*)  d_in[3];
    // d_in[4] = attention_mask (causal; applied analytically)
    const float* Wq   = (const float*)d_in[5];
    const float* Wk   = (const float*)d_in[6];
    const float* Wv   = (const float*)d_in[7];
    const float* Wo   = (const float*)d_in[8];
    const float* qw   = (const float*)d_in[9];
    const float* kw   = (const float*)d_in[10];
    float* out = (float*)d_out;

    const int gemm_smem = 2*GEMM_STAGE_F*4;              // 55296 B
    const int attn_smem = (2*4352 + 2*4608 + 128*68)*4;  // 106496 B
    cudaFuncSetAttribute(qkv_kernel, cudaFuncAttributeMaxDynamicSharedMemorySize, gemm_smem);
    cudaFuncSetAttribute(out_kernel, cudaFuncAttributeMaxDynamicSharedMemorySize, gemm_smem);
    cudaFuncSetAttribute(attn_kernel, cudaFuncAttributeMaxDynamicSharedMemorySize, attn_smem);

    cvt_kernel<<<6656, 256>>>(X, Wq, Wk, Wv, Wo);
    qkv_kernel<<<dim3(24, 32), 128, gemm_smem>>>(cosT, sinT, pos, qw, kw);
    attn_kernel<<<dim3(SS/128, NH, BB), 256, attn_smem>>>();
    out_kernel<<<dim3(16, 32), 128, gemm_smem>>>(out);
}

// round 4
// speedup vs baseline: 3.3095x; 1.0496x over previous
#include <cuda_runtime.h>

#define BB   2
#define SS   2048
#define HIDD 1024
#define NH   16
#define NKV  4
#define HD   64
#define SCALE 0.125f       // 1/sqrt(64)
#define SCL2 0.1803368801f // SCALE * log2(e)

// Scratch (static device globals — allocation-free)
__device__ float g_Q[BB*NH*SS*HD];        // 16 MB (tf32-rounded)
__device__ float g_K[BB*NKV*SS*HD];       //  4 MB (tf32-rounded)
__device__ float g_V[BB*NKV*SS*HD];       //  4 MB (tf32-rounded)
__device__ float g_CTX[BB*SS*NH*HD];      // 16 MB (tf32-rounded)
__device__ float g_Xt[BB*SS*HIDD];        // 16 MB tf32 copy of X
__device__ float g_Wt[1536*HIDD];         //  6 MB tf32 [Wq;Wk;Wv]
__device__ float g_Wot[HIDD*HIDD];        //  4 MB tf32 Wo

// ---------------------------------------------------------------------------
// helpers
// ---------------------------------------------------------------------------
__device__ __forceinline__ unsigned f2tf(float x) {
    unsigned r; asm("cvt.rna.tf32.f32 %0, %1;" : "=r"(r) : "f"(x)); return r;
}
__device__ __forceinline__ float f2tff(float x) { return __uint_as_float(f2tf(x)); }

__device__ __forceinline__ void mma8(float* c, const unsigned* a, const unsigned* b) {
    asm volatile(
        "mma.sync.aligned.m16n8k8.row.col.f32.tf32.tf32.f32 "
        "{%0,%1,%2,%3},{%4,%5,%6,%7},{%8,%9},{%0,%1,%2,%3};"
        : "+f"(c[0]), "+f"(c[1]), "+f"(c[2]), "+f"(c[3])
        : "r"(a[0]), "r"(a[1]), "r"(a[2]), "r"(a[3]), "r"(b[0]), "r"(b[1]));
}

__device__ __forceinline__ void cp16(float* dst, const float* src) {
    unsigned d = (unsigned)__cvta_generic_to_shared(dst);
    asm volatile("cp.async.cg.shared.global [%0], [%1], 16;\n" :: "r"(d), "l"(src));
}
__device__ __forceinline__ void cpcommit() { asm volatile("cp.async.commit_group;\n"); }
__device__ __forceinline__ void cpwait0()  { asm volatile("cp.async.wait_group 0;\n" ::: "memory"); }
__device__ __forceinline__ void cpwait1()  { asm volatile("cp.async.wait_group 1;\n" ::: "memory"); }

// ---------------------------------------------------------------------------
// Kernel 0: one-time tf32 rounding of X / Wq / Wk / Wv / Wo
// ---------------------------------------------------------------------------
__global__ __launch_bounds__(256) void cvt_kernel(
    const float* __restrict__ X,  const float* __restrict__ Wq,
    const float* __restrict__ Wk, const float* __restrict__ Wv,
    const float* __restrict__ Wo)
{
    long i = (long)blockIdx.x * 256 + threadIdx.x;   // float4 index
    const float4* src; float4* dst;
    if (i < 1048576L)       { src = (const float4*)X  + i;             dst = (float4*)g_Xt  + i; }
    else if (i < 1310720L)  { long j = i - 1048576L; src = (const float4*)Wq + j; dst = (float4*)g_Wt + j; }
    else if (i < 1376256L)  { long j = i - 1310720L; src = (const float4*)Wk + j; dst = (float4*)g_Wt + 262144L + j; }
    else if (i < 1441792L)  { long j = i - 1376256L; src = (const float4*)Wv + j; dst = (float4*)g_Wt + 327680L + j; }
    else                    { long j = i - 1441792L; src = (const float4*)Wo + j; dst = (float4*)g_Wot + j; }
    float4 v = *src;
    *dst = make_float4(f2tff(v.x), f2tff(v.y), f2tff(v.z), f2tff(v.w));
}

// ---------------------------------------------------------------------------
// GEMM core: block 128(M) x 128(N), BK=32, 256 threads = 8 warps (2m x 4n),
// warp tile 64x32.  2-stage cp.async pipeline, smem stride 36.
// stage s: As = sm + s*9216 (128x36), Bs = As + 4608 (128x36)
// ---------------------------------------------------------------------------
#define GEMM_STAGE_F 9216

__device__ __forceinline__ void gemm_stage(float* sm, int s, int k0,
                                           const float* A, const float* B, int tid)
{
    float* As = sm + s*GEMM_STAGE_F;
    float* Bs = As + 4608;
    #pragma unroll
    for (int q = 0; q < 4; q++) {
        int e = q*256 + tid; int r = e >> 3, c = (e & 7) << 2;
        cp16(As + r*36 + c, A + (long)r*HIDD + k0 + c);
    }
    #pragma unroll
    for (int q = 0; q < 4; q++) {
        int e = q*256 + tid; int r = e >> 3, c = (e & 7) << 2;
        cp16(Bs + r*36 + c, B + (long)r*HIDD + k0 + c);
    }
    cpcommit();
}

__device__ __forceinline__ void gemm_body(float* sm, const float* A, const float* B,
                                          float acc[4][4][4], int tid)
{
    const int lane = tid & 31, w = tid >> 5;
    const int g = lane >> 2, t = lane & 3;
    const int wm = (w >> 2) << 6;     // 0 or 64
    const int wn = (w & 3) << 5;      // 0,32,64,96

    gemm_stage(sm, 0, 0,  A, B, tid);
    gemm_stage(sm, 1, 32, A, B, tid);

    for (int kt = 0; kt < 32; kt++) {
        const int s = kt & 1;
        if (kt == 31) cpwait0(); else cpwait1();
        __syncthreads();
        const float* As = sm + s*GEMM_STAGE_F;
        const float* Bs = As + 4608;
        #pragma unroll
        for (int ks = 0; ks < 4; ks++) {
            const int kb = ks << 3;
            unsigned a[4][4], b[4][2];
            #pragma unroll
            for (int i = 0; i < 4; i++) {
                const float* p = &As[(wm + i*16 + g)*36 + kb + t];
                a[i][0] = __float_as_uint(p[0]);
                a[i][1] = __float_as_uint(p[8*36]);
                a[i][2] = __float_as_uint(p[4]);
                a[i][3] = __float_as_uint(p[8*36 + 4]);
            }
            #pragma unroll
            for (int j = 0; j < 4; j++) {
                const float* p = &Bs[(wn + j*8 + g)*36 + kb + t];
                b[j][0] = __float_as_uint(p[0]);
                b[j][1] = __float_as_uint(p[4]);
            }
            #pragma unroll
            for (int i = 0; i < 4; i++)
                #pragma unroll
                for (int j = 0; j < 4; j++)
                    mma8(acc[i][j], a[i], b[j]);
        }
        __syncthreads();
        if (kt + 2 < 32) gemm_stage(sm, s, (kt + 2) << 5, A, B, tid);
    }
}

// ---------------------------------------------------------------------------
// Kernel 1: QKV GEMM + per-head RMSNorm + RoPE epilogue
// N tiling: 8 Q-tiles (128 wide = 2 heads) + 2 K-tiles + 2 V-tiles
// ---------------------------------------------------------------------------
__global__ __launch_bounds__(256, 2) void qkv_kernel(
    const float* __restrict__ cosT, const float* __restrict__ sinT,
    const int*   __restrict__ pos,
    const float* __restrict__ qw, const float* __restrict__ kw)
{
    extern __shared__ float sm[];
    const int tid  = threadIdx.x;
    const int lane = tid & 31, w = tid >> 5;
    const int g = lane >> 2, t = lane & 3;
    const int wm = (w >> 2) << 6;
    const int wn = (w & 3) << 5;
    const int m0 = blockIdx.y << 7;
    const int n0 = blockIdx.x << 7;

    const float* A = g_Xt + (long)m0*HIDD;
    const float* B = g_Wt + (long)n0*HIDD;

    float acc[4][4][4];
    #pragma unroll
    for (int i = 0; i < 4; i++)
        #pragma unroll
        for (int j = 0; j < 4; j++)
            #pragma unroll
            for (int e = 0; e < 4; e++) acc[i][j][e] = 0.f;

    gemm_body(sm, A, B, acc, tid);

    // stage C to smem (stride 129) for row-wise epilogue
    __syncthreads();
    float* Cs = sm;
    #pragma unroll
    for (int i = 0; i < 4; i++)
        #pragma unroll
        for (int j = 0; j < 4; j++) {
            int r = wm + i*16 + g;
            int c = wn + j*8 + 2*t;
            Cs[r*129 + c]         = acc[i][j][0];
            Cs[r*129 + c + 1]     = acc[i][j][1];
            Cs[(r+8)*129 + c]     = acc[i][j][2];
            Cs[(r+8)*129 + c + 1] = acc[i][j][3];
        }
    __syncthreads();

    {
        const int r    = tid & 127;
        const int seg  = tid >> 7;          // 0/1: which 64-col head segment
        const int n    = n0 + (seg << 6);
        int mode, h;
        if (n < 1024)      { mode = 0; h = n >> 6; }
        else if (n < 1280) { mode = 1; h = (n-1024) >> 6; }
        else               { mode = 2; h = (n-1280) >> 6; }

        const int mrow = m0 + r;
        const int b    = mrow >> 11;
        const int srow = mrow & 2047;
        float* Crow = &Cs[r*129 + (seg << 6)];
        if (mode == 2) {
            float* dst = g_V + (((b*NKV + h)*SS + srow) << 6);
            #pragma unroll
            for (int d = 0; d < 64; d++) dst[d] = f2tff(Crow[d]);
        } else {
            float ssum = 0.f;
            #pragma unroll
            for (int d = 0; d < 64; d++) { float v = Crow[d]; ssum = fmaf(v, v, ssum); }
            const float rstd = rsqrtf(ssum * (1.f/64.f) + 1e-6f);
            const float* wn2 = (mode == 0) ? qw : kw;
            #pragma unroll
            for (int d = 0; d < 64; d++) Crow[d] = Crow[d] * rstd * wn2[d];
            const int p = pos[b*SS + srow];
            const float* cr = cosT + (p << 6);
            const float* sr = sinT + (p << 6);
            float* dst = (mode == 0) ? (g_Q + (((b*NH  + h)*SS + srow) << 6))
                                     : (g_K + (((b*NKV + h)*SS + srow) << 6));
            #pragma unroll
            for (int d = 0; d < 32; d++) {
                float x1 = Crow[d], x2 = Crow[d+32];
                dst[d]    = f2tff(x1*cr[d]    - x2*sr[d]);
                dst[d+32] = f2tff(x2*cr[d+32] + x1*sr[d+32]);
            }
        }
    }
}

// ---------------------------------------------------------------------------
// Kernel 2: causal flash attention, tf32 MMA, q-tile 128, 8 warps.
// smem: K[2][64*68] | V[2][64*72] | P[128*68]; cp.async double-buffered K/V.
// Softmax in exp2 domain (scores pre-scaled by SCALE*log2e).
// ---------------------------------------------------------------------------
__global__ __launch_bounds__(256, 2) void attn_kernel()
{
    extern __shared__ float sm[];
    float* Kb = sm;                    // [2][64*68]
    float* Vb = sm + 2*4352;           // [2][64*72]
    float* Ps = sm + 2*4352 + 2*4608;  // [128*68]

    const int tid  = threadIdx.x;
    const int lane = tid & 31;
    const int w    = tid >> 5;
    const int g = lane >> 2, t = lane & 3;
    const int qt = gridDim.x - 1 - blockIdx.x;   // heavy tiles first
    const int h = blockIdx.y, b = blockIdx.z;
    const int q0  = qt << 7;
    const int hkv = h >> 2;

    const float* Qg = g_Q + (((b*NH  + h  )*SS + q0 + w*16) << 6);
    const float* Kg = g_K + ( (b*NKV + hkv)*SS              << 6);
    const float* Vg = g_V + ( (b*NKV + hkv)*SS              << 6);

    // preload Q fragments (pre-rounded tf32)
    unsigned aq[8][4];
    #pragma unroll
    for (int ks = 0; ks < 8; ks++) {
        aq[ks][0] = __float_as_uint(Qg[ g      *64 + ks*8 + t]);
        aq[ks][1] = __float_as_uint(Qg[(g + 8) *64 + ks*8 + t]);
        aq[ks][2] = __float_as_uint(Qg[ g      *64 + ks*8 + t + 4]);
        aq[ks][3] = __float_as_uint(Qg[(g + 8) *64 + ks*8 + t + 4]);
    }

    float oacc[8][4];
    #pragma unroll
    for (int j = 0; j < 8; j++)
        #pragma unroll
        for (int e = 0; e < 4; e++) oacc[j][e] = 0.f;
    float m_lo = -1e30f, m_hi = -1e30f, l_lo = 0.f, l_hi = 0.f;

    const int nkt = 2*qt + 2;

    {   // prologue: stage tile 0 into buf 0
        #pragma unroll
        for (int q = 0; q < 4; q++) {
            int e = q*256 + tid; int r = e >> 4, c = (e & 15) << 2;
            cp16(Kb + r*68 + c, Kg + r*64 + c);
            cp16(Vb + r*72 + c, Vg + r*64 + c);
        }
        cpcommit();
    }

    for (int kt = 0; kt < nkt; kt++) {
        const int s = kt & 1;
        const bool hasNext = (kt + 1 < nkt);
        __syncthreads();
        if (hasNext) {
            const float* Kt = Kg + ((kt+1) << 12);
            const float* Vt = Vg + ((kt+1) << 12);
            float* Kd = Kb + (s^1)*4352;
            float* Vd = Vb + (s^1)*4608;
            #pragma unroll
            for (int q = 0; q < 4; q++) {
                int e = q*256 + tid; int r = e >> 4, c = (e & 15) << 2;
                cp16(Kd + r*68 + c, Kt + r*64 + c);
                cp16(Vd + r*72 + c, Vt + r*64 + c);
            }
            cpcommit();
            cpwait1();
        } else {
            cpwait0();
        }
        __syncthreads();

        if ((kt << 6) > q0 + w*16 + 15) continue;   // warp band fully masked

        const float* Kc = Kb + s*4352;
        const float* Vc = Vb + s*4608;

        // S = Q K^T : 16x64 per warp
        float sacc[8][4];
        #pragma unroll
        for (int j = 0; j < 8; j++)
            #pragma unroll
            for (int e = 0; e < 4; e++) sacc[j][e] = 0.f;
        #pragma unroll
        for (int ks = 0; ks < 8; ks++) {
            #pragma unroll
            for (int j = 0; j < 8; j++) {
                unsigned bk[2];
                const float* p = &Kc[(j*8 + g)*68 + ks*8 + t];
                bk[0] = __float_as_uint(p[0]);
                bk[1] = __float_as_uint(p[4]);
                mma8(sacc[j], aq[ks], bk);
            }
        }

        const bool diag = ((kt << 6) + 63 > q0 + w*16);
        float mx_lo = -1e30f, mx_hi = -1e30f;
        #pragma unroll
        for (int j = 0; j < 8; j++) {
            #pragma unroll
            for (int e = 0; e < 4; e++) {
                float s2 = sacc[j][e] * SCL2;      // log2-domain score
                if (diag) {
                    int c = (kt << 6) + j*8 + 2*t + (e & 1);
                    int r = q0 + w*16 + g + ((e >> 1) << 3);
                    if (c > r) s2 = -1e30f;
                }
                sacc[j][e] = s2;
            }
            mx_lo = fmaxf(mx_lo, fmaxf(sacc[j][0], sacc[j][1]));
            mx_hi = fmaxf(mx_hi, fmaxf(sacc[j][2], sacc[j][3]));
        }
        mx_lo = fmaxf(mx_lo, __shfl_xor_sync(0xffffffffu, mx_lo, 1));
        mx_lo = fmaxf(mx_lo, __shfl_xor_sync(0xffffffffu, mx_lo, 2));
        mx_hi = fmaxf(mx_hi, __shfl_xor_sync(0xffffffffu, mx_hi, 1));
        mx_hi = fmaxf(mx_hi, __shfl_xor_sync(0xffffffffu, mx_hi, 2));

        float nm_lo = fmaxf(m_lo, mx_lo), nm_hi = fmaxf(m_hi, mx_hi);
        float al_lo = exp2f(m_lo - nm_lo), al_hi = exp2f(m_hi - nm_hi);
        m_lo = nm_lo; m_hi = nm_hi;

        float sum_lo = 0.f, sum_hi = 0.f;
        #pragma unroll
        for (int j = 0; j < 8; j++) {
            sacc[j][0] = exp2f(sacc[j][0] - nm_lo);
            sacc[j][1] = exp2f(sacc[j][1] - nm_lo);
            sacc[j][2] = exp2f(sacc[j][2] - nm_hi);
            sacc[j][3] = exp2f(sacc[j][3] - nm_hi);
            sum_lo += sacc[j][0] + sacc[j][1];
            sum_hi += sacc[j][2] + sacc[j][3];
        }
        sum_lo += __shfl_xor_sync(0xffffffffu, sum_lo, 1);
        sum_lo += __shfl_xor_sync(0xffffffffu, sum_lo, 2);
        sum_hi += __shfl_xor_sync(0xffffffffu, sum_hi, 1);
        sum_hi += __shfl_xor_sync(0xffffffffu, sum_hi, 2);
        l_lo = l_lo*al_lo + sum_lo;
        l_hi = l_hi*al_hi + sum_hi;
        #pragma unroll
        for (int j = 0; j < 8; j++) {
            oacc[j][0] *= al_lo; oacc[j][1] *= al_lo;
            oacc[j][2] *= al_hi; oacc[j][3] *= al_hi;
        }

        // store P (tf32) into per-warp rows of the dedicated P buffer
        #pragma unroll
        for (int j = 0; j < 8; j++) {
            int c = j*8 + 2*t;
            int r = w*16 + g;
            Ps[r*68 + c]         = f2tff(sacc[j][0]);
            Ps[r*68 + c + 1]     = f2tff(sacc[j][1]);
            Ps[(r+8)*68 + c]     = f2tff(sacc[j][2]);
            Ps[(r+8)*68 + c + 1] = f2tff(sacc[j][3]);
        }
        __syncwarp();

        // O += P V : 16x64 per warp
        #pragma unroll
        for (int ks = 0; ks < 8; ks++) {
            unsigned ap[4];
            const float* p = &Ps[(w*16 + g)*68 + ks*8 + t];
            ap[0] = __float_as_uint(p[0]);
            ap[1] = __float_as_uint(p[8*68]);
            ap[2] = __float_as_uint(p[4]);
            ap[3] = __float_as_uint(p[8*68 + 4]);
            #pragma unroll
            for (int j = 0; j < 8; j++) {
                unsigned bv[2];
                const float* q = &Vc[(ks*8 + t)*72 + j*8 + g];
                bv[0] = __float_as_uint(q[0]);
                bv[1] = __float_as_uint(q[4*72]);
                mma8(oacc[j], ap, bv);
            }
        }
    }

    const float inv_lo = 1.f / l_lo, inv_hi = 1.f / l_hi;
    float* Cg = g_CTX + ((b*SS + q0 + w*16) << 10) + (h << 6);
    #pragma unroll
    for (int j = 0; j < 8; j++) {
        int c = j*8 + 2*t;
        float2 v0 = { f2tff(oacc[j][0]*inv_lo), f2tff(oacc[j][1]*inv_lo) };
        *(float2*)&Cg[g*1024 + c] = v0;
        float2 v1 = { f2tff(oacc[j][2]*inv_hi), f2tff(oacc[j][3]*inv_hi) };
        *(float2*)&Cg[(g+8)*1024 + c] = v1;
    }
}

// ---------------------------------------------------------------------------
// Kernel 3: output projection, direct fragment stores
// ---------------------------------------------------------------------------
__global__ __launch_bounds__(256, 2) void out_kernel(float* __restrict__ out)
{
    extern __shared__ float sm[];
    const int tid  = threadIdx.x;
    const int lane = tid & 31, w = tid >> 5;
    const int g = lane >> 2, t = lane & 3;
    const int wm = (w >> 2) << 6;
    const int wn = (w & 3) << 5;
    const int m0 = blockIdx.y << 7;
    const int n0 = blockIdx.x << 7;

    const float* A = g_CTX + (long)m0*HIDD;
    const float* B = g_Wot + (long)n0*HIDD;

    float acc[4][4][4];
    #pragma unroll
    for (int i = 0; i < 4; i++)
        #pragma unroll
        for (int j = 0; j < 4; j++)
            #pragma unroll
            for (int e = 0; e < 4; e++) acc[i][j][e] = 0.f;

    gemm_body(sm, A, B, acc, tid);

    #pragma unroll
    for (int i = 0; i < 4; i++)
        #pragma unroll
        for (int j = 0; j < 4; j++) {
            int r = m0 + wm + i*16 + g;
            int c = n0 + wn + j*8 + 2*t;
            float2 v0 = { acc[i][j][0], acc[i][j][1] };
            *(float2*)&out[(long)r*1024 + c] = v0;
            float2 v1 = { acc[i][j][2], acc[i][j][3] };
            *(float2*)&out[(long)(r+8)*1024 + c] = v1;
        }
}

// ---------------------------------------------------------------------------
extern "C" void kernel_launch(void* const* d_in, const int* in_sizes, int n_in,
                              void* d_out, int out_size)
{
    const float* X    = (const float*)d_in[0];
    const float* cosT = (const float*)d_in[1];
    const float* sinT = (const float*)d_in[2];
    const int*   pos  = (const int*)  d_in[3];
    // d_in[4] = attention_mask (causal; applied analytically)
    const float* Wq   = (const float*)d_in[5];
    const float* Wk   = (const float*)d_in[6];
    const float* Wv   = (const float*)d_in[7];
    const float* Wo   = (const float*)d_in[8];
    const float* qw   = (const float*)d_in[9];
    const float* kw   = (const float*)d_in[10];
    float* out = (float*)d_out;

    const int gemm_smem = 2*GEMM_STAGE_F*4;              // 73728 B
    const int attn_smem = (2*4352 + 2*4608 + 128*68)*4;  // 106496 B
    cudaFuncSetAttribute(qkv_kernel, cudaFuncAttributeMaxDynamicSharedMemorySize, gemm_smem);
    cudaFuncSetAttribute(out_kernel, cudaFuncAttributeMaxDynamicSharedMemorySize, gemm_smem);
    cudaFuncSetAttribute(attn_kernel, cudaFuncAttributeMaxDynamicSharedMemorySize, attn_smem);

    cvt_kernel<<<6656, 256>>>(X, Wq, Wk, Wv, Wo);
    qkv_kernel<<<dim3(12, 32), 256, gemm_smem>>>(cosT, sinT, pos, qw, kw);
    attn_kernel<<<dim3(SS/128, NH, BB), 256, attn_smem>>>();
    out_kernel<<<dim3(8, 32), 256, gemm_smem>>>(out);
}